// round 17
// baseline (speedup 1.0000x reference)
#include <cuda_runtime.h>

#define NB     16
#define NP     65536
#define NPTS   (NB * NP)                            // 1048576 points
#define RAD_N  5
#define AZI_N  30
#define ELE_N  15
#define KSL    (ELE_N - 1)                          // 14 ele pair-slots
#define PLANE_SLOTS (AZI_N * KSL)                   // 420 slots per (b,r) plane
#define PLANE_OUTS  (AZI_N * ELE_N)                 // 450 out bins per plane
#define NPLANE (NB * RAD_N)                         // 80 planes
#define NSLOT  (NPLANE * PLANE_SLOTS)               // 33600 float4 2x2-slots

#define NTHR   256
#define NBLK   (NPTS / 4 / NTHR)                    // 1024 blocks, 4 pts/thread

// 2x2 pair-slot histogram: slot[b][r][a][k] (a circular, k=0..13) holds
// contributions to bins (a,k),(a,k+1),(a+1%30,k),(a+1%30,k+1) in (.x,.y,.z,.w).
// INVARIANT: all-zero at kernel entry (zero-init at module load; the fold tail
// re-zeros after reading, so every graph replay sees a clean table).
__device__ float4 g_slots[NSLOT];

// Completion ticketing. g_gen is monotone across replays; g_done self-resets.
__device__ unsigned g_done = 0;
__device__ unsigned g_gen  = 0;

__device__ __forceinline__ void red_add4(float4* a, float x, float y, float z, float w) {
    asm volatile("red.global.add.v4.f32 [%0], {%1, %2, %3, %4};"
                 :: "l"(a), "f"(x), "f"(y), "f"(z), "f"(w) : "memory");
}

__device__ __forceinline__ void scatter_point(float x, float y, float z, int b) {
    float s = fmaf(x, x, fmaf(y, y, z * z));
    float rinv = rsqrtf(fmaxf(s, 1e-30f));      // MUFU.RSQ
    float r = s * rinv;
    if (r > 2.0f) return;   // reference culls r > DES_R

    // ---- azimuth DIRECTLY in bin units (x 30/2pi baked into poly) ----
    float ax = fabsf(x), ay = fabsf(y);
    float mx = fmaxf(ax, ay), mn = fminf(ax, ay);
    float t = __fdividef(mn, fmaxf(mx, 1e-30f));    // [0,1], MUFU-based
    float u = t * t;
    float p = -0.055964f;
    p = fmaf(p, u,  0.251395f);
    p = fmaf(p, u, -0.555922f);
    p = fmaf(p, u,  0.924098f);
    p = fmaf(p, u, -1.588168f);
    p = fmaf(p, u,  4.774540f);
    float th = t * p;                   // bins: atan in [0, 3.75]
    if (ay > ax)  th =  7.5f - th;
    if (x < 0.f)  th = 15.0f - th;
    if (y < 0.f)  th = 30.0f - th;      // [0, 30)

    // ---- elevation DIRECTLY in bin units: acos(c)*15/pi scaled A&S poly ----
    float c = fminf(fmaxf(z * rinv, -1.0f), 1.0f);
    float a = fabsf(c);
    float w = 1.0f - a;
    float sq = w * rsqrtf(fmaxf(w, 1e-30f));    // sqrt(w), exact 0 at w=0
    float q = -0.0060279f;
    q = fmaf(q, a,  0.0318469f);
    q = fmaf(q, a, -0.0815911f);
    q = fmaf(q, a,  0.1474978f);
    q = fmaf(q, a, -0.2395650f);
    q = fmaf(q, a,  0.4248380f);
    q = fmaf(q, a, -1.0246378f);
    q = fmaf(q, a,  7.4999999f);
    float acb = sq * q;                          // acos(a) in bins, [0, 7.5]
    float ve = (c >= 0.f) ? (acb - 0.5f) : (14.5f - acb);

    // radial pair: closed form of ref's half-bin boundary clamps
    float vr = fmaf(r, 2.5f, -0.5f);
    int jr; float wr0, wr1;
    if (vr < 0.f)        { jr = 0; wr0 = 1.f; wr1 = 0.f; }
    else if (vr >= 4.f)  { jr = 3; wr0 = 0.f; wr1 = 5.f - vr; }
    else { jr = __float2int_rd(vr); float f = vr - (float)jr; wr0 = 1.f - f; wr1 = f; }

    // azimuth pair: circular; slot sa covers bins (sa, sa+1 mod 30)
    float va = th - 0.5f;
    int   j  = __float2int_rd(va);      // in [-1, 29]
    float fa = va - (float)j;
    int sa = (j < 0) ? (AZI_N - 1) : j;
    float wa0 = 1.f - fa, wa1 = fa;

    // elevation pair: both-end half-bin clamps
    int ke; float we0, we1;
    if (ve < 0.f)         { ke = 0;  we0 = 1.f; we1 = 0.f; }
    else if (ve >= 14.f)  { ke = 13; we0 = 0.f; we1 = 1.f; }
    else { ke = __float2int_rd(ve); float f = ve - (float)ke; we0 = 1.f - f; we1 = f; }

    float p00 = wa0 * we0, p01 = wa0 * we1;
    float p10 = wa1 * we0, p11 = wa1 * we1;

    int s0 = ((b * RAD_N + jr) * AZI_N + sa) * KSL + ke;
    if (wr0 != 0.f)
        red_add4(&g_slots[s0], wr0 * p00, wr0 * p01, wr0 * p10, wr0 * p11);
    if (wr1 != 0.f)
        red_add4(&g_slots[s0 + PLANE_SLOTS], wr1 * p00, wr1 * p01, wr1 * p10, wr1 * p11);
}

__global__ void __launch_bounds__(NTHR) vox_kernel(const float* __restrict__ pts,
                                                   float* __restrict__ out) {
    __shared__ unsigned s_ticket;
    __shared__ float4 s[PLANE_SLOTS];

    // ---- Scatter: 4 points per thread via 3x float4 coalesced loads ----
    int g = blockIdx.x * NTHR + threadIdx.x;    // exact multiple, no guard
    const float4* p4 = (const float4*)pts;
    float4 A = __ldg(p4 + 3 * g);
    float4 B = __ldg(p4 + 3 * g + 1);
    float4 C = __ldg(p4 + 3 * g + 2);
    int b = (g * 4) >> 16;                      // 4 pts share batch (NP%4==0)

    scatter_point(A.x, A.y, A.z, b);
    scatter_point(A.w, B.x, B.y, b);
    scatter_point(B.z, B.w, C.x, b);
    scatter_point(C.y, C.z, C.w, b);

    // ---- Ticketing: last NPLANE blocks to finish become finishers ----
    __threadfence();          // make this block's reds globally visible
    __syncthreads();          // all warps' reds fenced before ticket
    if (threadIdx.x == 0) {
        // read gen BEFORE taking the ticket (flip only after last ticket)
        unsigned old = *(volatile unsigned*)&g_gen;
        unsigned t   = atomicAdd(&g_done, 1u);
        s_ticket = t;
        if (t == NBLK - 1) {
            atomicExch(&g_done, 0u);     // self-reset for next replay
            __threadfence();
            atomicAdd(&g_gen, 1u);       // release: all scatters complete
        } else if (t >= NBLK - NPLANE) {
            // spin on plain volatile load (no L2-atomic contention)
            while (*(volatile unsigned*)&g_gen == old) { __nanosleep(32); }
        }
        __threadfence();                 // acquire
    }
    __syncthreads();
    unsigned ticket = s_ticket;
    if (ticket < NBLK - NPLANE) return;  // non-finishers exit immediately

    // ---- Fold tail: this block owns one (b,r) plane; re-zeros slots ----
    int plane = (int)(ticket - (NBLK - NPLANE));
    float4* gp = g_slots + plane * PLANE_SLOTS;
    for (int i = threadIdx.x; i < PLANE_SLOTS; i += NTHR) {
        float4 v = __ldcg(&gp[i]);       // bypass L1: reds update L2 only
        s[i] = v;
        __stcg(&gp[i], make_float4(0.f, 0.f, 0.f, 0.f));  // restore invariant
    }
    __syncthreads();

    for (int i = threadIdx.x; i < PLANE_OUTS; i += NTHR) {
        int e   = i % ELE_N;
        int a   = i / ELE_N;
        int am1 = (a == 0) ? (AZI_N - 1) : (a - 1);

        float v = 0.f;
        if (e < KSL) {
            v += s[a   * KSL + e].x;
            v += s[am1 * KSL + e].z;
        }
        if (e > 0) {
            v += s[a   * KSL + e - 1].y;
            v += s[am1 * KSL + e - 1].w;
        }
        out[plane * PLANE_OUTS + i] = v;
    }
}

extern "C" void kernel_launch(void* const* d_in, const int* in_sizes, int n_in,
                              void* d_out, int out_size) {
    const float* pts = (const float*)d_in[0];
    float* out = (float*)d_out;
    vox_kernel<<<NBLK, NTHR>>>(pts, out);
}